// round 1
// baseline (speedup 1.0000x reference)
#include <cuda_runtime.h>

#define B_    32
#define T_    512
#define H_    256
#define WDIM_ 300

// ---------------- scratch (device globals; no allocation allowed) ----------------
__device__ __align__(16) float g_z[16384 * 256];                 // [r=t*32+b][256]   16 MB
__device__ __align__(16) float g_gates[2 * 512 * 1024 * 32];     // [dir][t][col][b] 128 MB
__device__ __align__(16) float g_h[2][2][256 * 32];              // [buf][dir][k][b]
__device__ __align__(16) float g_hsum[512 * 32];                 // [feat][b]
__device__ unsigned g_arrive[2];
__device__ unsigned g_gen[2];

// ---------------- helpers ----------------
__device__ __forceinline__ float sigf(float x) { return 1.0f / (1.0f + __expf(-x)); }

// Sense-reversing barrier among the 64 CTAs of one direction.
__device__ __forceinline__ void dir_barrier(int dir, unsigned ncta) {
    __syncthreads();
    if (threadIdx.x == 0) {
        unsigned old = atomicAdd(&g_gen[dir], 0u);   // read generation BEFORE arriving
        __threadfence();                             // order our h stores before arrival
        unsigned a = atomicAdd(&g_arrive[dir], 1u);
        if (a == ncta - 1u) {
            atomicExch(&g_arrive[dir], 0u);
            __threadfence();
            atomicAdd(&g_gen[dir], 1u);
        } else {
            while (atomicAdd(&g_gen[dir], 0u) == old) { }
        }
        __threadfence();
    }
    __syncthreads();
}

// ---------------- kernel 1: z = relu(emb[x] @ W_in + b_in), rows r = t*32 + b ----------------
__global__ void k1_embed(const float* __restrict__ emb, const float* __restrict__ Win,
                         const float* __restrict__ bin, const int* __restrict__ x) {
    __shared__ float As[4][68];
    __shared__ float Bs[4][68];
    __shared__ int   xid[64];
    int tid = threadIdx.x;
    int r0 = blockIdx.x * 64;
    int c0 = blockIdx.y * 64;
    if (tid < 64) {
        int r = r0 + tid;
        int b = r & 31, t = r >> 5;
        xid[tid] = x[b * T_ + t];
    }
    __syncthreads();
    int tx = tid & 15, ty = tid >> 4;
    float acc[4][4];
#pragma unroll
    for (int i = 0; i < 4; ++i)
#pragma unroll
        for (int j = 0; j < 4; ++j) acc[i][j] = 0.0f;

    int arr = tid >> 2, akk = tid & 3;       // A loader: row, k-sub
    int bkk = tid >> 6, bcc = tid & 63;      // B loader: k, col

    for (int k0 = 0; k0 < WDIM_; k0 += 4) {  // 300 = 75 * 4
        As[akk][arr] = emb[(size_t)xid[arr] * WDIM_ + (k0 + akk)];
        Bs[bkk][bcc] = Win[(size_t)(k0 + bkk) * H_ + c0 + bcc];
        __syncthreads();
#pragma unroll
        for (int kk = 0; kk < 4; ++kk) {
            float4 a  = *(const float4*)&As[kk][ty * 4];
            float4 bv = *(const float4*)&Bs[kk][tx * 4];
            float av[4] = {a.x, a.y, a.z, a.w};
            float bw[4] = {bv.x, bv.y, bv.z, bv.w};
#pragma unroll
            for (int i = 0; i < 4; ++i)
#pragma unroll
                for (int j = 0; j < 4; ++j) acc[i][j] += av[i] * bw[j];
        }
        __syncthreads();
    }
    float bj[4];
#pragma unroll
    for (int j = 0; j < 4; ++j) bj[j] = bin[c0 + tx * 4 + j];
#pragma unroll
    for (int i = 0; i < 4; ++i) {
        int r = r0 + ty * 4 + i;
        float4 v;
        v.x = fmaxf(acc[i][0] + bj[0], 0.0f);
        v.y = fmaxf(acc[i][1] + bj[1], 0.0f);
        v.z = fmaxf(acc[i][2] + bj[2], 0.0f);
        v.w = fmaxf(acc[i][3] + bj[3], 0.0f);
        *(float4*)&g_z[(size_t)r * H_ + c0 + tx * 4] = v;
    }
}

// ---------------- kernel 2: gates[dir][t][col][b] = z @ Wih_dir + bl_dir ----------------
__global__ void k2_gates(const float* __restrict__ Wf, const float* __restrict__ blf,
                         const float* __restrict__ Wb, const float* __restrict__ blb) {
    __shared__ float As[16][68];
    __shared__ float Bs[16][68];
    int tid = threadIdx.x;
    int r0  = blockIdx.x * 64;
    int cg0 = blockIdx.y * 64;
    int dir = cg0 >> 10;
    int c0  = cg0 & 1023;
    const float* W  = dir ? Wb : Wf;
    const float* bl = dir ? blb : blf;
    int tx = tid & 15, ty = tid >> 4;
    float acc[4][4];
#pragma unroll
    for (int i = 0; i < 4; ++i)
#pragma unroll
        for (int j = 0; j < 4; ++j) acc[i][j] = 0.0f;

    int arr = tid >> 2, aks = (tid & 3) * 4;
    int bkk = tid >> 4, bcs = (tid & 15) * 4;

    for (int k0 = 0; k0 < H_; k0 += 16) {
        float4 av = *(const float4*)&g_z[(size_t)(r0 + arr) * H_ + k0 + aks];
        float4 bv = *(const float4*)&W[(size_t)(k0 + bkk) * 1024 + c0 + bcs];
        As[aks + 0][arr] = av.x;
        As[aks + 1][arr] = av.y;
        As[aks + 2][arr] = av.z;
        As[aks + 3][arr] = av.w;
        *(float4*)&Bs[bkk][bcs] = bv;
        __syncthreads();
#pragma unroll
        for (int kk = 0; kk < 16; ++kk) {
            float4 a = *(const float4*)&As[kk][ty * 4];
            float4 b = *(const float4*)&Bs[kk][tx * 4];
            float av2[4] = {a.x, a.y, a.z, a.w};
            float bw[4]  = {b.x, b.y, b.z, b.w};
#pragma unroll
            for (int i = 0; i < 4; ++i)
#pragma unroll
                for (int j = 0; j < 4; ++j) acc[i][j] += av2[i] * bw[j];
        }
        __syncthreads();
    }
    int rbase = r0 + ty * 4;
    int t  = rbase >> 5;
    int bb = rbase & 31;   // multiple of 4, no wrap across i
#pragma unroll
    for (int j = 0; j < 4; ++j) {
        int c = c0 + tx * 4 + j;
        float bias = bl[c];
        float4 v = make_float4(acc[0][j] + bias, acc[1][j] + bias,
                               acc[2][j] + bias, acc[3][j] + bias);
        *(float4*)&g_gates[(size_t)(((dir * 512 + t) * 1024 + c) * 32 + bb)] = v;
    }
}

// ---------------- kernel 3: persistent bidirectional LSTM recurrence ----------------
// 128 CTAs: dir = cta>>6, slice = cta&63 owns hidden units [slice*4, slice*4+4).
// smem: w_s[256][16] (Whh slice, persistent) | h_s[256][32] (aliased by red[8][16*33]).
__global__ void __launch_bounds__(256, 1)
k3_lstm(const float* __restrict__ Whhf, const float* __restrict__ Whhb,
        const int* __restrict__ mask) {
    __shared__ float sm[12288];           // 48 KB exactly
    float* w_s = sm;                      // 4096 floats
    float* h_s = sm + 4096;               // 8192 floats
    float* red = sm + 4096;               // aliased: 8*528 = 4224 floats

    int cta   = blockIdx.x;
    int dir   = cta >> 6;
    int slice = cta & 63;
    int u0    = slice << 2;
    const float* Whh = dir ? Whhb : Whhf;
    int tid  = threadIdx.x;
    int warp = tid >> 5, lane = tid & 31;

    // persistent Whh slice: w_s[k][lc], lc = g*4+u -> global col g*256 + u0 + u
    for (int i = tid; i < 4096; i += 256) {
        int k = i >> 4, lc = i & 15;
        w_s[i] = Whh[(size_t)k * 1024 + (lc >> 2) * 256 + u0 + (lc & 3)];
    }

    int u = tid >> 5;        // valid for tid < 128
    int b = tid & 31;
    float c_reg = 0.0f, h_reg = 0.0f, hsum_reg = 0.0f;
    if (tid < 128) g_h[0][dir][(u0 + u) * 32 + b] = 0.0f;
    dir_barrier(dir, 64);    // zeros + w_s visible everywhere

    int lc4 = (lane & 3) << 2;
    int b4  = (lane >> 2) << 2;
    int kbase = warp << 5;

    for (int t = 0; t < T_; ++t) {
        int cur = t & 1, nxt = cur ^ 1;
        int tt = dir ? (T_ - 1 - t) : t;

        // prefetch gate preactivations + mask early (DRAM latency hidden behind GEMM)
        float gpre0 = 0.f, gpre1 = 0.f, gpre2 = 0.f, gpre3 = 0.f, mval = 0.f;
        if (tid < 128) {
            const float* gp = g_gates + (size_t)(dir * 512 + tt) * (1024 * 32);
            gpre0 = gp[(0 * 256 + u0 + u) * 32 + b];
            gpre1 = gp[(1 * 256 + u0 + u) * 32 + b];
            gpre2 = gp[(2 * 256 + u0 + u) * 32 + b];
            gpre3 = gp[(3 * 256 + u0 + u) * 32 + b];
            mval  = (float)mask[b * T_ + tt];
        }

        // copy h (L2-coherent) into smem, transposed layout [k][b]
        {
            const float4* src = (const float4*)g_h[cur][dir];
            float4* dst = (float4*)h_s;
#pragma unroll
            for (int i = 0; i < 8; ++i) dst[tid + (i << 8)] = __ldcg(src + tid + (i << 8));
        }
        __syncthreads();

        // z_slice[32][16] = h @ Whh_slice, k split across 8 warps
        float acc[4][4];
#pragma unroll
        for (int i = 0; i < 4; ++i)
#pragma unroll
            for (int j = 0; j < 4; ++j) acc[i][j] = 0.0f;
#pragma unroll
        for (int kk = 0; kk < 32; ++kk) {
            int k = kbase + kk;
            float4 hv = *(const float4*)&h_s[(k << 5) + b4];
            float4 wv = *(const float4*)&w_s[(k << 4) + lc4];
            float hb[4] = {hv.x, hv.y, hv.z, hv.w};
            float wc[4] = {wv.x, wv.y, wv.z, wv.w};
#pragma unroll
            for (int i = 0; i < 4; ++i)
#pragma unroll
                for (int j = 0; j < 4; ++j) acc[i][j] += hb[i] * wc[j];
        }
        __syncthreads();   // everyone done reading h_s before red (alias) is written
#pragma unroll
        for (int i = 0; i < 4; ++i)
#pragma unroll
            for (int j = 0; j < 4; ++j)
                red[warp * 528 + (lc4 + j) * 33 + (b4 + i)] = acc[i][j];
        __syncthreads();

        if (tid < 128) {
            float z0 = gpre0, z1 = gpre1, z2 = gpre2, z3 = gpre3;
#pragma unroll
            for (int w = 0; w < 8; ++w) {
                const float* rp = red + w * 528 + b;
                z0 += rp[(0 + u) * 33];
                z1 += rp[(4 + u) * 33];
                z2 += rp[(8 + u) * 33];
                z3 += rp[(12 + u) * 33];
            }
            float ig = sigf(z0), fg = sigf(z1);
            float gg = tanhf(z2), og = sigf(z3);
            float cn = fg * c_reg + ig * gg;
            float hn = og * tanhf(cn);
            c_reg = mval * cn + (1.0f - mval) * c_reg;
            h_reg = mval * hn + (1.0f - mval) * h_reg;
            hsum_reg += mval * h_reg;
            g_h[nxt][dir][(u0 + u) * 32 + b] = h_reg;
        }
        dir_barrier(dir, 64);
    }
    if (tid < 128) g_hsum[((dir << 8) + u0 + u) * 32 + b] = hsum_reg;
}

// ---------------- kernel 4: mean-pool already done; FC + output ----------------
__global__ void k4_out(const float* __restrict__ Wfc, const float* __restrict__ bfc,
                       const float* __restrict__ Wout, const float* __restrict__ bout,
                       const int* __restrict__ lengths, float* __restrict__ out) {
    __shared__ float hs[512];
    __shared__ float r0s[8], r1s[8];
    int b = blockIdx.x, tid = threadIdx.x;
    float invlen = 1.0f / (float)lengths[b];
    for (int f = tid; f < 512; f += 256) hs[f] = g_hsum[f * 32 + b] * invlen;
    __syncthreads();
    int j = tid;
    float a = bfc[j];
#pragma unroll 8
    for (int f = 0; f < 512; ++f) a += hs[f] * Wfc[(size_t)f * 256 + j];
    a = fmaxf(a, 0.0f);
    float p0 = a * Wout[j * 2 + 0];
    float p1 = a * Wout[j * 2 + 1];
#pragma unroll
    for (int off = 16; off > 0; off >>= 1) {
        p0 += __shfl_down_sync(0xffffffffu, p0, off);
        p1 += __shfl_down_sync(0xffffffffu, p1, off);
    }
    if ((tid & 31) == 0) { r0s[tid >> 5] = p0; r1s[tid >> 5] = p1; }
    __syncthreads();
    if (tid == 0) {
        float s0 = bout[0], s1 = bout[1];
#pragma unroll
        for (int w = 0; w < 8; ++w) { s0 += r0s[w]; s1 += r1s[w]; }
        out[b * 2 + 0] = s0;
        out[b * 2 + 1] = s1;
    }
}

// ---------------- launch ----------------
extern "C" void kernel_launch(void* const* d_in, const int* in_sizes, int n_in,
                              void* d_out, int out_size) {
    const float* emb  = (const float*)d_in[0];
    const float* Win  = (const float*)d_in[1];
    const float* bin  = (const float*)d_in[2];
    const float* Wihf = (const float*)d_in[3];
    const float* Whhf = (const float*)d_in[4];
    const float* blf  = (const float*)d_in[5];
    const float* Wihb = (const float*)d_in[6];
    const float* Whhb = (const float*)d_in[7];
    const float* blb  = (const float*)d_in[8];
    const float* Wfc  = (const float*)d_in[9];
    const float* bfc  = (const float*)d_in[10];
    const float* Wout = (const float*)d_in[11];
    const float* bout = (const float*)d_in[12];
    const int*   x    = (const int*)d_in[13];
    const int*   mask = (const int*)d_in[14];
    const int*   len  = (const int*)d_in[15];
    float* out = (float*)d_out;

    k1_embed<<<dim3(256, 4), 256>>>(emb, Win, bin, x);
    k2_gates<<<dim3(256, 32), 256>>>(Wihf, blf, Wihb, blb);
    k3_lstm<<<128, 256>>>(Whhf, Whhb, mask);
    k4_out<<<32, 256>>>(Wfc, bfc, Wout, bout, len, out);
}

// round 2
// speedup vs baseline: 1.0174x; 1.0174x over previous
#include <cuda_runtime.h>

#define B_    32
#define T_    512
#define H_    256
#define WDIM_ 300

typedef unsigned long long u64;

// ---------------- scratch (device globals; no allocation allowed) ----------------
__device__ __align__(16) float g_z[16384 * 256];                 // [r=t*32+b][256]   16 MB
__device__ __align__(16) float g_gates[2 * 512 * 1024 * 32];     // [dir][t][col][b] 128 MB
__device__ __align__(16) float g_h[2][2][256 * 32];              // [buf][dir][k][b]
__device__ __align__(16) float g_hsum[512 * 32];                 // [feat][b]
__device__ __align__(16) float g_fc[256 * 32];                   // [j][b]
__device__ unsigned g_arrive[2];
__device__ unsigned g_gen[2];

// ---------------- f32x2 packed-FMA helpers (exact fp32 semantics) ----------------
__device__ __forceinline__ u64 pk(float lo, float hi) {
    u64 r; asm("mov.b64 %0, {%1, %2};" : "=l"(r) : "f"(lo), "f"(hi)); return r;
}
__device__ __forceinline__ u64 dupf(float v) {
    u64 r; asm("mov.b64 %0, {%1, %1};" : "=l"(r) : "f"(v)); return r;
}
__device__ __forceinline__ void fma2(u64& d, u64 a, u64 b) {
    asm("fma.rn.f32x2 %0, %1, %2, %0;" : "+l"(d) : "l"(a), "l"(b));
}
__device__ __forceinline__ float2 upk(u64 v) {
    float2 f; asm("mov.b64 {%0, %1}, %2;" : "=f"(f.x), "=f"(f.y) : "l"(v)); return f;
}

__device__ __forceinline__ float sigf(float x) { return 1.0f / (1.0f + __expf(-x)); }

// Sense-reversing barrier among the 64 CTAs of one direction (graph-replay safe).
__device__ __forceinline__ void dir_barrier(int dir, unsigned ncta) {
    __syncthreads();
    if (threadIdx.x == 0) {
        volatile unsigned* gen = &g_gen[dir];
        unsigned old = *gen;                 // no arrival this round can precede ours
        __threadfence();                     // order our h stores before arrival
        unsigned a = atomicAdd(&g_arrive[dir], 1u);
        if (a == ncta - 1u) {
            g_arrive[dir] = 0u;
            __threadfence();
            atomicExch((unsigned*)&g_gen[dir], old + 1u);
        } else {
            while (*gen == old) { }
        }
        __threadfence();
    }
    __syncthreads();
}

// ---------------- kernel 1: z = relu(emb[x] @ W_in + b_in), rows r = t*32 + b ----------------
// 64x64 block tile, 4x4 per thread (f32x2-packed), K-tile 12 (300 = 25*12).
__global__ void k1_embed(const float* __restrict__ emb, const float* __restrict__ Win,
                         const float* __restrict__ bin, const int* __restrict__ x) {
    __shared__ float As[12][68];
    __shared__ float Bs[12][68];
    __shared__ int   xid[64];
    int tid = threadIdx.x;
    int r0 = blockIdx.x * 64;
    int c0 = blockIdx.y * 64;
    if (tid < 64) {
        int r = r0 + tid;
        int b = r & 31, t = r >> 5;
        xid[tid] = x[b * T_ + t];
    }
    __syncthreads();
    int tx = tid & 15, ty = tid >> 4;
    u64 acc2[2][4];
#pragma unroll
    for (int p = 0; p < 2; ++p)
#pragma unroll
        for (int j = 0; j < 4; ++j) acc2[p][j] = 0ULL;

    int ar = tid >> 2, ag = (tid & 3) * 3;       // A loader: row, k-group of 3
    int bc = tid & 63, bg = (tid >> 6) * 3;      // B loader: col, k-group of 3

    for (int k0 = 0; k0 < WDIM_; k0 += 12) {
        const float* ep = emb + (size_t)xid[ar] * WDIM_ + k0 + ag;
        As[ag + 0][ar] = ep[0];
        As[ag + 1][ar] = ep[1];
        As[ag + 2][ar] = ep[2];
#pragma unroll
        for (int j = 0; j < 3; ++j)
            Bs[bg + j][bc] = Win[(size_t)(k0 + bg + j) * H_ + c0 + bc];
        __syncthreads();
#pragma unroll
        for (int kk = 0; kk < 12; ++kk) {
            float4 a  = *(const float4*)&As[kk][ty * 4];
            float4 bv = *(const float4*)&Bs[kk][tx * 4];
            u64 ap0 = pk(a.x, a.y), ap1 = pk(a.z, a.w);
            u64 bd0 = dupf(bv.x), bd1 = dupf(bv.y), bd2 = dupf(bv.z), bd3 = dupf(bv.w);
            fma2(acc2[0][0], ap0, bd0); fma2(acc2[0][1], ap0, bd1);
            fma2(acc2[0][2], ap0, bd2); fma2(acc2[0][3], ap0, bd3);
            fma2(acc2[1][0], ap1, bd0); fma2(acc2[1][1], ap1, bd1);
            fma2(acc2[1][2], ap1, bd2); fma2(acc2[1][3], ap1, bd3);
        }
        __syncthreads();
    }
    float bj[4];
#pragma unroll
    for (int j = 0; j < 4; ++j) bj[j] = bin[c0 + tx * 4 + j];
#pragma unroll
    for (int p = 0; p < 2; ++p) {
        float2 u[4];
#pragma unroll
        for (int j = 0; j < 4; ++j) u[j] = upk(acc2[p][j]);
        int r = r0 + ty * 4 + p * 2;
        float4 v0 = make_float4(fmaxf(u[0].x + bj[0], 0.f), fmaxf(u[1].x + bj[1], 0.f),
                                fmaxf(u[2].x + bj[2], 0.f), fmaxf(u[3].x + bj[3], 0.f));
        float4 v1 = make_float4(fmaxf(u[0].y + bj[0], 0.f), fmaxf(u[1].y + bj[1], 0.f),
                                fmaxf(u[2].y + bj[2], 0.f), fmaxf(u[3].y + bj[3], 0.f));
        *(float4*)&g_z[(size_t)r * H_ + c0 + tx * 4]       = v0;
        *(float4*)&g_z[(size_t)(r + 1) * H_ + c0 + tx * 4] = v1;
    }
}

// ---------------- kernel 2: gates[dir][t][col][b] = z @ Wih_dir + bl_dir ----------------
// 128x64 block tile, 8x4 per thread (f32x2-packed along rows), K-tile 16.
__global__ void __launch_bounds__(256)
k2_gates(const float* __restrict__ Wf, const float* __restrict__ blf,
         const float* __restrict__ Wb, const float* __restrict__ blb) {
    __shared__ float As[16][132];
    __shared__ float Bs[16][68];
    int tid = threadIdx.x;
    int r0  = blockIdx.x * 128;
    int cg0 = blockIdx.y * 64;
    int dir = cg0 >> 10;
    int c0  = cg0 & 1023;
    const float* W  = dir ? Wb : Wf;
    const float* bl = dir ? blb : blf;
    int i0 = (tid >> 4) * 8;     // 16 row-groups of 8
    int j0 = (tid & 15) * 4;     // 16 col-groups of 4

    u64 acc2[4][4];
#pragma unroll
    for (int p = 0; p < 4; ++p)
#pragma unroll
        for (int j = 0; j < 4; ++j) acc2[p][j] = 0ULL;

    int bkb = tid >> 4, bcb = (tid & 15) * 4;    // B loader

    for (int k0 = 0; k0 < H_; k0 += 16) {
        // A: 128 rows x 16 k, transposed store into As[k][row]
#pragma unroll
        for (int q = 0; q < 2; ++q) {
            int s  = tid + q * 256;
            int rr = s & 127, kq = s >> 7;
            float4 v = *(const float4*)&g_z[(size_t)(r0 + rr) * H_ + k0 + kq * 4];
            As[kq * 4 + 0][rr] = v.x;
            As[kq * 4 + 1][rr] = v.y;
            As[kq * 4 + 2][rr] = v.z;
            As[kq * 4 + 3][rr] = v.w;
        }
        // B: 16 k x 64 cols
        {
            float4 v = *(const float4*)&W[(size_t)(k0 + bkb) * 1024 + c0 + bcb];
            *(float4*)&Bs[bkb][bcb] = v;
        }
        __syncthreads();
#pragma unroll
        for (int kk = 0; kk < 16; ++kk) {
            float4 a0 = *(const float4*)&As[kk][i0];
            float4 a1 = *(const float4*)&As[kk][i0 + 4];
            float4 bv = *(const float4*)&Bs[kk][j0];
            u64 ap[4] = {pk(a0.x, a0.y), pk(a0.z, a0.w), pk(a1.x, a1.y), pk(a1.z, a1.w)};
            u64 bd[4] = {dupf(bv.x), dupf(bv.y), dupf(bv.z), dupf(bv.w)};
#pragma unroll
            for (int p = 0; p < 4; ++p) {
                fma2(acc2[p][0], ap[p], bd[0]);
                fma2(acc2[p][1], ap[p], bd[1]);
                fma2(acc2[p][2], ap[p], bd[2]);
                fma2(acc2[p][3], ap[p], bd[3]);
            }
        }
        __syncthreads();
    }
    // rows r = r0 + i0 + (0..7): same t (i0 multiple of 8, r0 multiple of 128)
    int rbase = r0 + i0;
    int t  = rbase >> 5;
    int b0 = rbase & 31;
#pragma unroll
    for (int j = 0; j < 4; ++j) {
        int c = c0 + j0 + j;
        float bias = bl[c];
        float2 u0 = upk(acc2[0][j]), u1 = upk(acc2[1][j]);
        float2 u2 = upk(acc2[2][j]), u3 = upk(acc2[3][j]);
        float* gp = g_gates + (size_t)(((dir * 512 + t) * 1024 + c) * 32 + b0);
        *(float4*)gp       = make_float4(u0.x + bias, u0.y + bias, u1.x + bias, u1.y + bias);
        *(float4*)(gp + 4) = make_float4(u2.x + bias, u2.y + bias, u3.x + bias, u3.y + bias);
    }
}

// ---------------- kernel 3: persistent bidirectional LSTM recurrence ----------------
// 128 CTAs: dir = cta>>6, slice = cta&63 owns hidden units [slice*4, slice*4+4).
// smem: w_s[256][16] (Whh slice, persistent) | h_s[256][32] (aliased by red[8][16*33]).
__global__ void __launch_bounds__(256, 1)
k3_lstm(const float* __restrict__ Whhf, const float* __restrict__ Whhb,
        const int* __restrict__ mask) {
    __shared__ float sm[12288];           // 48 KB exactly
    float* w_s = sm;                      // 4096 floats
    float* h_s = sm + 4096;               // 8192 floats
    float* red = sm + 4096;               // aliased: 8*528 = 4224 floats

    int cta   = blockIdx.x;
    int dir   = cta >> 6;
    int slice = cta & 63;
    int u0    = slice << 2;
    const float* Whh = dir ? Whhb : Whhf;
    int tid  = threadIdx.x;
    int warp = tid >> 5, lane = tid & 31;

    // persistent Whh slice: w_s[k][lc], lc = g*4+u -> global col g*256 + u0 + u
    for (int i = tid; i < 4096; i += 256) {
        int k = i >> 4, lc = i & 15;
        w_s[i] = Whh[(size_t)k * 1024 + (lc >> 2) * 256 + u0 + (lc & 3)];
    }

    int u = tid >> 5;        // valid for tid < 128
    int b = tid & 31;
    float c_reg = 0.0f, h_reg = 0.0f, hsum_reg = 0.0f;
    if (tid < 128) g_h[0][dir][(u0 + u) * 32 + b] = 0.0f;
    dir_barrier(dir, 64);    // zeros + w_s visible everywhere

    int lc4 = (lane & 3) << 2;
    int b4  = (lane >> 2) << 2;
    int kbase = warp << 5;

    for (int t = 0; t < T_; ++t) {
        int cur = t & 1, nxt = cur ^ 1;
        int tt = dir ? (T_ - 1 - t) : t;

        // prefetch gate preactivations + mask early
        float gpre0 = 0.f, gpre1 = 0.f, gpre2 = 0.f, gpre3 = 0.f, mval = 0.f;
        if (tid < 128) {
            const float* gp = g_gates + (size_t)(dir * 512 + tt) * (1024 * 32);
            gpre0 = gp[(0 * 256 + u0 + u) * 32 + b];
            gpre1 = gp[(1 * 256 + u0 + u) * 32 + b];
            gpre2 = gp[(2 * 256 + u0 + u) * 32 + b];
            gpre3 = gp[(3 * 256 + u0 + u) * 32 + b];
            mval  = (float)mask[b * T_ + tt];
        }

        // copy h (L2-coherent) into smem, layout [k][b]
        {
            const float4* src = (const float4*)g_h[cur][dir];
            float4* dst = (float4*)h_s;
#pragma unroll
            for (int i = 0; i < 8; ++i) dst[tid + (i << 8)] = __ldcg(src + tid + (i << 8));
        }
        __syncthreads();

        // z_slice[32][16] = h @ Whh_slice, k split across 8 warps (f32x2-packed)
        u64 acc2[2][4];
#pragma unroll
        for (int p = 0; p < 2; ++p)
#pragma unroll
            for (int j = 0; j < 4; ++j) acc2[p][j] = 0ULL;
#pragma unroll
        for (int kk = 0; kk < 32; ++kk) {
            int k = kbase + kk;
            float4 hv = *(const float4*)&h_s[(k << 5) + b4];
            float4 wv = *(const float4*)&w_s[(k << 4) + lc4];
            u64 hp0 = pk(hv.x, hv.y), hp1 = pk(hv.z, hv.w);
            u64 wd0 = dupf(wv.x), wd1 = dupf(wv.y), wd2 = dupf(wv.z), wd3 = dupf(wv.w);
            fma2(acc2[0][0], hp0, wd0); fma2(acc2[0][1], hp0, wd1);
            fma2(acc2[0][2], hp0, wd2); fma2(acc2[0][3], hp0, wd3);
            fma2(acc2[1][0], hp1, wd0); fma2(acc2[1][1], hp1, wd1);
            fma2(acc2[1][2], hp1, wd2); fma2(acc2[1][3], hp1, wd3);
        }
        __syncthreads();   // everyone done reading h_s before red (alias) is written
#pragma unroll
        for (int p = 0; p < 2; ++p)
#pragma unroll
            for (int j = 0; j < 4; ++j) {
                float2 v = upk(acc2[p][j]);
                red[warp * 528 + (lc4 + j) * 33 + (b4 + 2 * p + 0)] = v.x;
                red[warp * 528 + (lc4 + j) * 33 + (b4 + 2 * p + 1)] = v.y;
            }
        __syncthreads();

        if (tid < 128) {
            float z0 = gpre0, z1 = gpre1, z2 = gpre2, z3 = gpre3;
#pragma unroll
            for (int w = 0; w < 8; ++w) {
                const float* rp = red + w * 528 + b;
                z0 += rp[(0 + u) * 33];
                z1 += rp[(4 + u) * 33];
                z2 += rp[(8 + u) * 33];
                z3 += rp[(12 + u) * 33];
            }
            float ig = sigf(z0), fg = sigf(z1);
            float gg = tanhf(z2), og = sigf(z3);
            float cn = fg * c_reg + ig * gg;
            float hn = og * tanhf(cn);
            c_reg = mval * cn + (1.0f - mval) * c_reg;
            h_reg = mval * hn + (1.0f - mval) * h_reg;
            hsum_reg += mval * h_reg;
            g_h[nxt][dir][(u0 + u) * 32 + b] = h_reg;
        }
        dir_barrier(dir, 64);
    }
    if (tid < 128) g_hsum[((dir << 8) + u0 + u) * 32 + b] = hsum_reg;
}

// ---------------- kernel 4a: fc_hidden[j][b] = relu(invlen_b * sum_f hsum[f][b]*Wfc[f][j] + bfc[j]) ----------------
// 32 CTAs, each owns 8 j-columns for all 32 b: Wfc read exactly once chip-wide.
__global__ void k4a_fc(const float* __restrict__ Wfc, const float* __restrict__ bfc,
                       const int* __restrict__ lengths) {
    int tid = threadIdx.x;
    int jj = tid >> 5, b = tid & 31;
    int j = blockIdx.x * 8 + jj;
    float invlen = 1.0f / (float)lengths[b];
    float acc = 0.0f;
#pragma unroll 8
    for (int f = 0; f < 512; ++f)
        acc += g_hsum[f * 32 + b] * Wfc[(size_t)f * 256 + j];
    float v = fmaxf(acc * invlen + bfc[j], 0.0f);
    g_fc[j * 32 + b] = v;
}

// ---------------- kernel 4b: logits ----------------
__global__ void k4b_out(const float* __restrict__ Wout, const float* __restrict__ bout,
                        float* __restrict__ out) {
    int t = threadIdx.x;       // 64 threads: b = t>>1, label = t&1
    int b = t >> 1, lab = t & 1;
    float s = bout[lab];
#pragma unroll 8
    for (int j = 0; j < 256; ++j)
        s += g_fc[j * 32 + b] * Wout[j * 2 + lab];
    out[b * 2 + lab] = s;
}

// ---------------- launch ----------------
extern "C" void kernel_launch(void* const* d_in, const int* in_sizes, int n_in,
                              void* d_out, int out_size) {
    const float* emb  = (const float*)d_in[0];
    const float* Win  = (const float*)d_in[1];
    const float* bin  = (const float*)d_in[2];
    const float* Wihf = (const float*)d_in[3];
    const float* Whhf = (const float*)d_in[4];
    const float* blf  = (const float*)d_in[5];
    const float* Wihb = (const float*)d_in[6];
    const float* Whhb = (const float*)d_in[7];
    const float* blb  = (const float*)d_in[8];
    const float* Wfc  = (const float*)d_in[9];
    const float* bfc  = (const float*)d_in[10];
    const float* Wout = (const float*)d_in[11];
    const float* bout = (const float*)d_in[12];
    const int*   x    = (const int*)d_in[13];
    const int*   mask = (const int*)d_in[14];
    const int*   len  = (const int*)d_in[15];
    float* out = (float*)d_out;

    k1_embed<<<dim3(256, 4), 256>>>(emb, Win, bin, x);
    k2_gates<<<dim3(128, 32), 256>>>(Wihf, blf, Wihb, blb);
    k3_lstm<<<128, 256>>>(Whhf, Whhb, mask);
    k4a_fc<<<32, 256>>>(Wfc, bfc, len);
    k4b_out<<<1, 64>>>(Wout, bout, out);
}

// round 3
// speedup vs baseline: 1.3745x; 1.3510x over previous
#include <cuda_runtime.h>

#define B_    32
#define T_    512
#define H_    256
#define WDIM_ 300

typedef unsigned long long u64;

// ---------------- scratch (device globals; no allocation allowed) ----------------
__device__ __align__(16) float g_z[16384 * 256];                 // [r=t*32+b][256]   16 MB
__device__ __align__(16) float g_gates[2 * 512 * 1024 * 32];     // [dir][t][col][b] 128 MB
__device__ __align__(16) float g_h[2][2][256 * 32];              // [buf][dir][k][b]
__device__ __align__(16) float g_hsum[512 * 32];                 // [feat][b]
__device__ __align__(16) float g_fc[256 * 32];                   // [j][b]
__device__ unsigned g_arrive[2];
__device__ unsigned g_gen[2];
__device__ __align__(128) unsigned g_flags[2][64];               // monotonic publish counters

// ---------------- f32x2 packed-FMA helpers (exact fp32 semantics) ----------------
__device__ __forceinline__ u64 pk(float lo, float hi) {
    u64 r; asm("mov.b64 %0, {%1, %2};" : "=l"(r) : "f"(lo), "f"(hi)); return r;
}
__device__ __forceinline__ u64 dupf(float v) {
    u64 r; asm("mov.b64 %0, {%1, %1};" : "=l"(r) : "f"(v)); return r;
}
__device__ __forceinline__ void fma2(u64& d, u64 a, u64 b) {
    asm("fma.rn.f32x2 %0, %1, %2, %0;" : "+l"(d) : "l"(a), "l"(b));
}
__device__ __forceinline__ float2 upk(u64 v) {
    float2 f; asm("mov.b64 {%0, %1}, %2;" : "=f"(f.x), "=f"(f.y) : "l"(v)); return f;
}

__device__ __forceinline__ float sigf(float x) { return 1.0f / (1.0f + __expf(-x)); }

__device__ __forceinline__ unsigned ldacq(const unsigned* p) {
    unsigned v;
    asm volatile("ld.acquire.gpu.global.u32 %0, [%1];" : "=r"(v) : "l"(p) : "memory");
    return v;
}
__device__ __forceinline__ void red_release_add1(unsigned* p) {
    asm volatile("red.release.gpu.global.add.u32 [%0], 1;" :: "l"(p) : "memory");
}

// Sense-reversing barrier among the 64 CTAs of one direction (used ONCE at start).
__device__ __forceinline__ void dir_barrier(int dir, unsigned ncta) {
    __syncthreads();
    if (threadIdx.x == 0) {
        volatile unsigned* gen = &g_gen[dir];
        unsigned old = *gen;
        __threadfence();
        unsigned a = atomicAdd(&g_arrive[dir], 1u);
        if (a == ncta - 1u) {
            g_arrive[dir] = 0u;
            __threadfence();
            atomicExch((unsigned*)&g_gen[dir], old + 1u);
        } else {
            while (*gen == old) { }
        }
        __threadfence();
    }
    __syncthreads();
}

// ---------------- kernel 1: z = relu(emb[x] @ W_in + b_in), rows r = t*32 + b ----------------
__global__ void k1_embed(const float* __restrict__ emb, const float* __restrict__ Win,
                         const float* __restrict__ bin, const int* __restrict__ x) {
    __shared__ float As[12][68];
    __shared__ float Bs[12][68];
    __shared__ int   xid[64];
    int tid = threadIdx.x;
    int r0 = blockIdx.x * 64;
    int c0 = blockIdx.y * 64;
    if (tid < 64) {
        int r = r0 + tid;
        int b = r & 31, t = r >> 5;
        xid[tid] = x[b * T_ + t];
    }
    __syncthreads();
    int tx = tid & 15, ty = tid >> 4;
    u64 acc2[2][4];
#pragma unroll
    for (int p = 0; p < 2; ++p)
#pragma unroll
        for (int j = 0; j < 4; ++j) acc2[p][j] = 0ULL;

    int ar = tid >> 2, ag = (tid & 3) * 3;
    int bc = tid & 63, bg = (tid >> 6) * 3;

    for (int k0 = 0; k0 < WDIM_; k0 += 12) {
        const float* ep = emb + (size_t)xid[ar] * WDIM_ + k0 + ag;
        As[ag + 0][ar] = ep[0];
        As[ag + 1][ar] = ep[1];
        As[ag + 2][ar] = ep[2];
#pragma unroll
        for (int j = 0; j < 3; ++j)
            Bs[bg + j][bc] = Win[(size_t)(k0 + bg + j) * H_ + c0 + bc];
        __syncthreads();
#pragma unroll
        for (int kk = 0; kk < 12; ++kk) {
            float4 a  = *(const float4*)&As[kk][ty * 4];
            float4 bv = *(const float4*)&Bs[kk][tx * 4];
            u64 ap0 = pk(a.x, a.y), ap1 = pk(a.z, a.w);
            u64 bd0 = dupf(bv.x), bd1 = dupf(bv.y), bd2 = dupf(bv.z), bd3 = dupf(bv.w);
            fma2(acc2[0][0], ap0, bd0); fma2(acc2[0][1], ap0, bd1);
            fma2(acc2[0][2], ap0, bd2); fma2(acc2[0][3], ap0, bd3);
            fma2(acc2[1][0], ap1, bd0); fma2(acc2[1][1], ap1, bd1);
            fma2(acc2[1][2], ap1, bd2); fma2(acc2[1][3], ap1, bd3);
        }
        __syncthreads();
    }
    float bj[4];
#pragma unroll
    for (int j = 0; j < 4; ++j) bj[j] = bin[c0 + tx * 4 + j];
#pragma unroll
    for (int p = 0; p < 2; ++p) {
        float2 u[4];
#pragma unroll
        for (int j = 0; j < 4; ++j) u[j] = upk(acc2[p][j]);
        int r = r0 + ty * 4 + p * 2;
        float4 v0 = make_float4(fmaxf(u[0].x + bj[0], 0.f), fmaxf(u[1].x + bj[1], 0.f),
                                fmaxf(u[2].x + bj[2], 0.f), fmaxf(u[3].x + bj[3], 0.f));
        float4 v1 = make_float4(fmaxf(u[0].y + bj[0], 0.f), fmaxf(u[1].y + bj[1], 0.f),
                                fmaxf(u[2].y + bj[2], 0.f), fmaxf(u[3].y + bj[3], 0.f));
        *(float4*)&g_z[(size_t)r * H_ + c0 + tx * 4]       = v0;
        *(float4*)&g_z[(size_t)(r + 1) * H_ + c0 + tx * 4] = v1;
    }
}

// ---------------- kernel 2: gates[dir][t][col][b] = z @ Wih_dir + bl_dir ----------------
__global__ void __launch_bounds__(256)
k2_gates(const float* __restrict__ Wf, const float* __restrict__ blf,
         const float* __restrict__ Wb, const float* __restrict__ blb) {
    __shared__ float As[16][132];
    __shared__ float Bs[16][68];
    int tid = threadIdx.x;
    int r0  = blockIdx.x * 128;
    int cg0 = blockIdx.y * 64;
    int dir = cg0 >> 10;
    int c0  = cg0 & 1023;
    const float* W  = dir ? Wb : Wf;
    const float* bl = dir ? blb : blf;
    int i0 = (tid >> 4) * 8;
    int j0 = (tid & 15) * 4;

    u64 acc2[4][4];
#pragma unroll
    for (int p = 0; p < 4; ++p)
#pragma unroll
        for (int j = 0; j < 4; ++j) acc2[p][j] = 0ULL;

    int bkb = tid >> 4, bcb = (tid & 15) * 4;

    for (int k0 = 0; k0 < H_; k0 += 16) {
#pragma unroll
        for (int q = 0; q < 2; ++q) {
            int s  = tid + q * 256;
            int rr = s & 127, kq = s >> 7;
            float4 v = *(const float4*)&g_z[(size_t)(r0 + rr) * H_ + k0 + kq * 4];
            As[kq * 4 + 0][rr] = v.x;
            As[kq * 4 + 1][rr] = v.y;
            As[kq * 4 + 2][rr] = v.z;
            As[kq * 4 + 3][rr] = v.w;
        }
        {
            float4 v = *(const float4*)&W[(size_t)(k0 + bkb) * 1024 + c0 + bcb];
            *(float4*)&Bs[bkb][bcb] = v;
        }
        __syncthreads();
#pragma unroll
        for (int kk = 0; kk < 16; ++kk) {
            float4 a0 = *(const float4*)&As[kk][i0];
            float4 a1 = *(const float4*)&As[kk][i0 + 4];
            float4 bv = *(const float4*)&Bs[kk][j0];
            u64 ap[4] = {pk(a0.x, a0.y), pk(a0.z, a0.w), pk(a1.x, a1.y), pk(a1.z, a1.w)};
            u64 bd[4] = {dupf(bv.x), dupf(bv.y), dupf(bv.z), dupf(bv.w)};
#pragma unroll
            for (int p = 0; p < 4; ++p) {
                fma2(acc2[p][0], ap[p], bd[0]);
                fma2(acc2[p][1], ap[p], bd[1]);
                fma2(acc2[p][2], ap[p], bd[2]);
                fma2(acc2[p][3], ap[p], bd[3]);
            }
        }
        __syncthreads();
    }
    int rbase = r0 + i0;
    int t  = rbase >> 5;
    int b0 = rbase & 31;
#pragma unroll
    for (int j = 0; j < 4; ++j) {
        int c = c0 + j0 + j;
        float bias = bl[c];
        float2 u0 = upk(acc2[0][j]), u1 = upk(acc2[1][j]);
        float2 u2 = upk(acc2[2][j]), u3 = upk(acc2[3][j]);
        float* gp = g_gates + (size_t)(((dir * 512 + t) * 1024 + c) * 32 + b0);
        *(float4*)gp       = make_float4(u0.x + bias, u0.y + bias, u1.x + bias, u1.y + bias);
        *(float4*)(gp + 4) = make_float4(u2.x + bias, u2.y + bias, u3.x + bias, u3.y + bias);
    }
}

// ---------------- kernel 3: persistent bidirectional LSTM recurrence ----------------
// 128 CTAs: dir = cta>>6, slice = cta&63 owns hidden units [slice*4, slice*4+4).
// Per-step sync: one-way release/acquire flags (monotonic, graph-replay safe).
__global__ void __launch_bounds__(256, 1)
k3_lstm(const float* __restrict__ Whhf, const float* __restrict__ Whhb,
        const int* __restrict__ mask) {
    __shared__ float sm[12288];           // 48 KB
    float* w_s = sm;                      // 4096 floats
    float* h_s = sm + 4096;               // 8192 floats
    float* red = sm + 4096;               // aliased: 8*528

    int cta   = blockIdx.x;
    int dir   = cta >> 6;
    int slice = cta & 63;
    int u0    = slice << 2;
    const float* Whh = dir ? Whhb : Whhf;
    int tid  = threadIdx.x;
    int warp = tid >> 5, lane = tid & 31;

    for (int i = tid; i < 4096; i += 256) {
        int k = i >> 4, lc = i & 15;
        w_s[i] = Whh[(size_t)k * 1024 + (lc >> 2) * 256 + u0 + (lc & 3)];
    }

    int u = tid >> 5;        // valid for tid < 128
    int b = tid & 31;
    float c_reg = 0.0f, h_reg = 0.0f, hsum_reg = 0.0f;
    if (tid < 128) g_h[0][dir][(u0 + u) * 32 + b] = 0.0f;

    // flag base: all flags equal at launch (each CTA adds exactly 128*512 per run).
    unsigned base = 0;
    const unsigned* myflag = 0;
    if (tid >= 192) {
        myflag = &g_flags[dir][tid - 192];
        base = ldacq(myflag);
    }
    dir_barrier(dir, 64);    // zeros + w_s + base reads complete before any publish

    int lc4 = (lane & 3) << 2;
    int b4  = (lane >> 2) << 2;
    int kbase = warp << 5;
    unsigned* pubflag = &g_flags[dir][slice];

    for (int t = 0; t < T_; ++t) {
        int cur = t & 1, nxt = cur ^ 1;
        int tt = dir ? (T_ - 1 - t) : t;

        // prefetch gate preactivations + mask (independent of h; in flight during spin)
        float gpre0 = 0.f, gpre1 = 0.f, gpre2 = 0.f, gpre3 = 0.f, mval = 0.f;
        if (tid < 128) {
            const float* gp = g_gates + (size_t)(dir * 512 + tt) * (1024 * 32);
            gpre0 = gp[(0 * 256 + u0 + u) * 32 + b];
            gpre1 = gp[(1 * 256 + u0 + u) * 32 + b];
            gpre2 = gp[(2 * 256 + u0 + u) * 32 + b];
            gpre3 = gp[(3 * 256 + u0 + u) * 32 + b];
            mval  = (float)mask[b * T_ + tt];
        }

        // wait: all 64 producers published h(t)  (each iteration adds 128 to its flag)
        if (tid >= 192) {
            unsigned need = 128u * (unsigned)t;
            while (ldacq(myflag) - base < need) { }
        }
        __syncthreads();

        // copy h (L2-coherent) into smem, layout [k][b]
        {
            const float4* src = (const float4*)g_h[cur][dir];
            float4* dst = (float4*)h_s;
#pragma unroll
            for (int i = 0; i < 8; ++i) dst[tid + (i << 8)] = __ldcg(src + tid + (i << 8));
        }
        __syncthreads();

        // z_slice[32][16] = h @ Whh_slice, k split across 8 warps (f32x2-packed)
        u64 acc2[2][4];
#pragma unroll
        for (int p = 0; p < 2; ++p)
#pragma unroll
            for (int j = 0; j < 4; ++j) acc2[p][j] = 0ULL;
#pragma unroll
        for (int kk = 0; kk < 32; ++kk) {
            int k = kbase + kk;
            float4 hv = *(const float4*)&h_s[(k << 5) + b4];
            float4 wv = *(const float4*)&w_s[(k << 4) + lc4];
            u64 hp0 = pk(hv.x, hv.y), hp1 = pk(hv.z, hv.w);
            u64 wd0 = dupf(wv.x), wd1 = dupf(wv.y), wd2 = dupf(wv.z), wd3 = dupf(wv.w);
            fma2(acc2[0][0], hp0, wd0); fma2(acc2[0][1], hp0, wd1);
            fma2(acc2[0][2], hp0, wd2); fma2(acc2[0][3], hp0, wd3);
            fma2(acc2[1][0], hp1, wd0); fma2(acc2[1][1], hp1, wd1);
            fma2(acc2[1][2], hp1, wd2); fma2(acc2[1][3], hp1, wd3);
        }
        __syncthreads();   // all reads of h_s done before red (alias) is written
#pragma unroll
        for (int p = 0; p < 2; ++p)
#pragma unroll
            for (int j = 0; j < 4; ++j) {
                float2 v = upk(acc2[p][j]);
                red[warp * 528 + (lc4 + j) * 33 + (b4 + 2 * p + 0)] = v.x;
                red[warp * 528 + (lc4 + j) * 33 + (b4 + 2 * p + 1)] = v.y;
            }
        __syncthreads();

        if (tid < 128) {
            float z0 = gpre0, z1 = gpre1, z2 = gpre2, z3 = gpre3;
#pragma unroll
            for (int w = 0; w < 8; ++w) {
                const float* rp = red + w * 528 + b;
                z0 += rp[(0 + u) * 33];
                z1 += rp[(4 + u) * 33];
                z2 += rp[(8 + u) * 33];
                z3 += rp[(12 + u) * 33];
            }
            float ig = sigf(z0), fg = sigf(z1);
            float gg = tanhf(z2), og = sigf(z3);
            float cn = fg * c_reg + ig * gg;
            float hn = og * tanhf(cn);
            c_reg = mval * cn + (1.0f - mval) * c_reg;
            h_reg = mval * hn + (1.0f - mval) * h_reg;
            hsum_reg += mval * h_reg;
            g_h[nxt][dir][(u0 + u) * 32 + b] = h_reg;
            // publish: release-add orders this thread's h store before the count bump
            red_release_add1(pubflag);
        }
    }
    if (tid < 128) g_hsum[((dir << 8) + u0 + u) * 32 + b] = hsum_reg;
}

// ---------------- kernel 4a: fc_hidden[j][b], one CTA per j, K split over 8 warps ----------------
__global__ void k4a_fc(const float* __restrict__ Wfc, const float* __restrict__ bfc,
                       const int* __restrict__ lengths) {
    __shared__ float redsm[8][32];
    int j = blockIdx.x;
    int tid = threadIdx.x;
    int w = tid >> 5, lane = tid & 31;
    float acc = 0.0f;
    int f0 = w * 64;
#pragma unroll 8
    for (int f = f0; f < f0 + 64; ++f)
        acc += g_hsum[f * 32 + lane] * Wfc[(size_t)f * 256 + j];
    redsm[w][lane] = acc;
    __syncthreads();
    if (w == 0) {
        float s = 0.0f;
#pragma unroll
        for (int q = 0; q < 8; ++q) s += redsm[q][lane];
        float invlen = 1.0f / (float)lengths[lane];
        g_fc[j * 32 + lane] = fmaxf(s * invlen + bfc[j], 0.0f);
    }
}

// ---------------- kernel 4b: logits ----------------
__global__ void k4b_out(const float* __restrict__ Wout, const float* __restrict__ bout,
                        float* __restrict__ out) {
    int t = threadIdx.x;
    int b = t >> 1, lab = t & 1;
    float s = bout[lab];
#pragma unroll 8
    for (int j = 0; j < 256; ++j)
        s += g_fc[j * 32 + b] * Wout[j * 2 + lab];
    out[b * 2 + lab] = s;
}

// ---------------- launch ----------------
extern "C" void kernel_launch(void* const* d_in, const int* in_sizes, int n_in,
                              void* d_out, int out_size) {
    const float* emb  = (const float*)d_in[0];
    const float* Win  = (const float*)d_in[1];
    const float* bin  = (const float*)d_in[2];
    const float* Wihf = (const float*)d_in[3];
    const float* Whhf = (const float*)d_in[4];
    const float* blf  = (const float*)d_in[5];
    const float* Wihb = (const float*)d_in[6];
    const float* Whhb = (const float*)d_in[7];
    const float* blb  = (const float*)d_in[8];
    const float* Wfc  = (const float*)d_in[9];
    const float* bfc  = (const float*)d_in[10];
    const float* Wout = (const float*)d_in[11];
    const float* bout = (const float*)d_in[12];
    const int*   x    = (const int*)d_in[13];
    const int*   mask = (const int*)d_in[14];
    const int*   len  = (const int*)d_in[15];
    float* out = (float*)d_out;

    k1_embed<<<dim3(256, 4), 256>>>(emb, Win, bin, x);
    k2_gates<<<dim3(128, 32), 256>>>(Wihf, blf, Wihb, blb);
    k3_lstm<<<128, 256>>>(Whhf, Whhb, mask);
    k4a_fc<<<256, 256>>>(Wfc, bfc, len);
    k4b_out<<<1, 64>>>(Wout, bout, out);
}

// round 5
// speedup vs baseline: 1.5007x; 1.0917x over previous
#include <cuda_runtime.h>
#include <cuda_bf16.h>
#include <cstdint>

#define B_    32
#define T_    512
#define H_    256
#define WDIM_ 300

typedef unsigned long long u64;

// ---------------- scratch (device globals; no allocation allowed) ----------------
__device__ __align__(16) __nv_bfloat16 g_zhi[16384 * 256];       // z split hi  [r][k]
__device__ __align__(16) __nv_bfloat16 g_zlo[16384 * 256];       // z split lo  [r][k]
__device__ __align__(16) __nv_bfloat16 g_wt[2][2][1024][256];    // [dir][part][c][k]
__device__ __align__(16) float g_gates[2 * 512 * 1024 * 32];     // [dir][t][col][b] 128 MB
__device__ __align__(16) float g_h[2][2][256 * 32];              // [buf][dir][k][b]
__device__ __align__(16) float g_hsum[512 * 32];                 // [feat][b]
__device__ __align__(16) float g_fc[256 * 32];                   // [j][b]
__device__ unsigned g_arrive[2];
__device__ unsigned g_gen[2];
__device__ __align__(128) unsigned g_flags[2][64];               // monotonic publish counters

// ---------------- f32x2 helpers (exact fp32 semantics) ----------------
__device__ __forceinline__ u64 pk(float lo, float hi) {
    u64 r; asm("mov.b64 %0, {%1, %2};" : "=l"(r) : "f"(lo), "f"(hi)); return r;
}
__device__ __forceinline__ u64 dupf(float v) {
    u64 r; asm("mov.b64 %0, {%1, %1};" : "=l"(r) : "f"(v)); return r;
}
__device__ __forceinline__ void fma2(u64& d, u64 a, u64 b) {
    asm("fma.rn.f32x2 %0, %1, %2, %0;" : "+l"(d) : "l"(a), "l"(b));
}
__device__ __forceinline__ float2 upk(u64 v) {
    float2 f; asm("mov.b64 {%0, %1}, %2;" : "=f"(f.x), "=f"(f.y) : "l"(v)); return f;
}

__device__ __forceinline__ float sigf(float x) { return 1.0f / (1.0f + __expf(-x)); }

__device__ __forceinline__ unsigned ldacq(const unsigned* p) {
    unsigned v;
    asm volatile("ld.acquire.gpu.global.u32 %0, [%1];" : "=r"(v) : "l"(p) : "memory");
    return v;
}
__device__ __forceinline__ void red_release_add1(unsigned* p) {
    asm volatile("red.release.gpu.global.add.u32 [%0], 1;" :: "l"(p) : "memory");
}

// warp-level bf16 MMA (sm_80+ baseline feature; works on compute_103)
__device__ __forceinline__ void mma16816(float* c, const unsigned* a, unsigned b0, unsigned b1) {
    asm volatile(
        "mma.sync.aligned.m16n8k16.row.col.f32.bf16.bf16.f32 "
        "{%0,%1,%2,%3}, {%4,%5,%6,%7}, {%8,%9}, {%0,%1,%2,%3};"
        : "+f"(c[0]), "+f"(c[1]), "+f"(c[2]), "+f"(c[3])
        : "r"(a[0]), "r"(a[1]), "r"(a[2]), "r"(a[3]), "r"(b0), "r"(b1));
}

// Sense-reversing barrier among the 64 CTAs of one direction (used ONCE at start of k3).
__device__ __forceinline__ void dir_barrier(int dir, unsigned ncta) {
    __syncthreads();
    if (threadIdx.x == 0) {
        volatile unsigned* gen = &g_gen[dir];
        unsigned old = *gen;
        __threadfence();
        unsigned a = atomicAdd(&g_arrive[dir], 1u);
        if (a == ncta - 1u) {
            g_arrive[dir] = 0u;
            __threadfence();
            atomicExch((unsigned*)&g_gen[dir], old + 1u);
        } else {
            while (*gen == old) { }
        }
        __threadfence();
    }
    __syncthreads();
}

// ---------------- kernel 1: z = relu(emb[x] @ W_in + b_in) -> bf16 hi/lo ----------------
__global__ void k1_embed(const float* __restrict__ emb, const float* __restrict__ Win,
                         const float* __restrict__ bin, const int* __restrict__ x) {
    __shared__ float As[12][68];
    __shared__ float Bs[12][68];
    __shared__ int   xid[64];
    int tid = threadIdx.x;
    int r0 = blockIdx.x * 64;
    int c0 = blockIdx.y * 64;
    if (tid < 64) {
        int r = r0 + tid;
        int b = r & 31, t = r >> 5;
        xid[tid] = x[b * T_ + t];
    }
    __syncthreads();
    int tx = tid & 15, ty = tid >> 4;
    u64 acc2[2][4];
#pragma unroll
    for (int p = 0; p < 2; ++p)
#pragma unroll
        for (int j = 0; j < 4; ++j) acc2[p][j] = 0ULL;

    int ar = tid >> 2, ag = (tid & 3) * 3;
    int bc = tid & 63, bg = (tid >> 6) * 3;

    for (int k0 = 0; k0 < WDIM_; k0 += 12) {
        const float* ep = emb + (size_t)xid[ar] * WDIM_ + k0 + ag;
        As[ag + 0][ar] = ep[0];
        As[ag + 1][ar] = ep[1];
        As[ag + 2][ar] = ep[2];
#pragma unroll
        for (int j = 0; j < 3; ++j)
            Bs[bg + j][bc] = Win[(size_t)(k0 + bg + j) * H_ + c0 + bc];
        __syncthreads();
#pragma unroll
        for (int kk = 0; kk < 12; ++kk) {
            float4 a  = *(const float4*)&As[kk][ty * 4];
            float4 bv = *(const float4*)&Bs[kk][tx * 4];
            u64 ap0 = pk(a.x, a.y), ap1 = pk(a.z, a.w);
            u64 bd0 = dupf(bv.x), bd1 = dupf(bv.y), bd2 = dupf(bv.z), bd3 = dupf(bv.w);
            fma2(acc2[0][0], ap0, bd0); fma2(acc2[0][1], ap0, bd1);
            fma2(acc2[0][2], ap0, bd2); fma2(acc2[0][3], ap0, bd3);
            fma2(acc2[1][0], ap1, bd0); fma2(acc2[1][1], ap1, bd1);
            fma2(acc2[1][2], ap1, bd2); fma2(acc2[1][3], ap1, bd3);
        }
        __syncthreads();
    }
    float bj[4];
#pragma unroll
    for (int j = 0; j < 4; ++j) bj[j] = bin[c0 + tx * 4 + j];
#pragma unroll
    for (int p = 0; p < 2; ++p) {
        float2 uu[4];
#pragma unroll
        for (int j = 0; j < 4; ++j) uu[j] = upk(acc2[p][j]);
        float vr[2][4];
#pragma unroll
        for (int j = 0; j < 4; ++j) {
            vr[0][j] = fmaxf(uu[j].x + bj[j], 0.0f);
            vr[1][j] = fmaxf(uu[j].y + bj[j], 0.0f);
        }
#pragma unroll
        for (int q = 0; q < 2; ++q) {
            int r = r0 + ty * 4 + p * 2 + q;
            size_t base = (size_t)r * 256 + c0 + tx * 4;
            __nv_bfloat16 h[4], l[4];
#pragma unroll
            for (int j = 0; j < 4; ++j) {
                h[j] = __float2bfloat16(vr[q][j]);
                l[j] = __float2bfloat16(vr[q][j] - __bfloat162float(h[j]));
            }
            *(__nv_bfloat162*)&g_zhi[base]     = __nv_bfloat162{h[0], h[1]};
            *(__nv_bfloat162*)&g_zhi[base + 2] = __nv_bfloat162{h[2], h[3]};
            *(__nv_bfloat162*)&g_zlo[base]     = __nv_bfloat162{l[0], l[1]};
            *(__nv_bfloat162*)&g_zlo[base + 2] = __nv_bfloat162{l[2], l[3]};
        }
    }
}

// ---------------- kernel 2w: split/transpose Wih -> g_wt[dir][part][c][k] ----------------
__global__ void k2w_conv(const float* __restrict__ Wf, const float* __restrict__ Wb) {
    int gid = blockIdx.x * 256 + threadIdx.x;     // 2*1024*256 total
    int k = gid & 255;
    int c = (gid >> 8) & 1023;
    int dir = gid >> 18;
    float w = (dir ? Wb : Wf)[(size_t)k * 1024 + c];
    __nv_bfloat16 hi = __float2bfloat16(w);
    __nv_bfloat16 lo = __float2bfloat16(w - __bfloat162float(hi));
    g_wt[dir][0][c][k] = hi;
    g_wt[dir][1][c][k] = lo;
}

// ---------------- kernel 2: HMMA bf16-split GEMM: gates = z @ Wih + bl ----------------
// grid (128, 16): r0 = bx*128; by 0..7 -> dir0 col-tiles, 8..15 -> dir1.
// CTA tile 128x128. 8 warps: wm = wid&3 (M rows of 32), wn = wid>>2 (N cols of 64).
// K loop: 3 segments (hi*Whi, hi*Wlo, lo*Whi) x 4 chunks of 64.
#define AS_STRIDE 72
__global__ void __launch_bounds__(256) k2_hmma(const float* __restrict__ blf,
                                               const float* __restrict__ blb) {
    __shared__ __align__(16) unsigned char smraw[2 * 128 * AS_STRIDE * 2];
    __nv_bfloat16* As = (__nv_bfloat16*)smraw;                       // [128][72]
    __nv_bfloat16* Bs = As + 128 * AS_STRIDE;                        // [128][72]
    float* Sc = (float*)smraw;                                       // epilogue: [8 warps][8][33]

    int tid = threadIdx.x;
    int wid = tid >> 5, lane = tid & 31;
    int g = lane >> 2, tg = lane & 3;
    int wm = wid & 3, wn = wid >> 2;
    int bx = blockIdx.x, by = blockIdx.y;
    int dir = by >> 3;
    int c0  = (by & 7) * 128;
    int r0  = bx * 128;

    int lrow = tid >> 1;          // copy: 128 rows, 2 threads/row
    int lhalf = tid & 1;          // 64B halves

    float c[2][8][4];
#pragma unroll
    for (int mi = 0; mi < 2; ++mi)
#pragma unroll
        for (int ni = 0; ni < 8; ++ni)
#pragma unroll
            for (int q = 0; q < 4; ++q) c[mi][ni][q] = 0.0f;

    int m0 = wm * 32;
    int n0 = wn * 64;

    for (int seg = 0; seg < 3; ++seg) {
        const __nv_bfloat16* Ag = (seg < 2) ? g_zhi : g_zlo;
        const __nv_bfloat16* Bg = &g_wt[dir][(seg == 1) ? 1 : 0][c0][0];

        for (int chunk = 0; chunk < 4; ++chunk) {
            int k0 = chunk * 64;
            // load A chunk: 128 rows x 64 bf16 (128B/row)
            {
                const uint4* src = (const uint4*)(Ag + (size_t)(r0 + lrow) * 256 + k0 + lhalf * 32);
                uint4* dst = (uint4*)(As + lrow * AS_STRIDE + lhalf * 32);
#pragma unroll
                for (int q = 0; q < 4; ++q) dst[q] = src[q];
            }
            // load B chunk: 128 n-rows x 64 bf16
            {
                const uint4* src = (const uint4*)(Bg + (size_t)lrow * 256 + k0 + lhalf * 32);
                uint4* dst = (uint4*)(Bs + lrow * AS_STRIDE + lhalf * 32);
#pragma unroll
                for (int q = 0; q < 4; ++q) dst[q] = src[q];
            }
            __syncthreads();

#pragma unroll
            for (int ks = 0; ks < 4; ++ks) {
                int k1 = ks * 16;
                unsigned a[2][4];
#pragma unroll
                for (int mi = 0; mi < 2; ++mi) {
                    const __nv_bfloat16* ab = As + (m0 + mi * 16 + g) * AS_STRIDE + k1 + tg * 2;
                    a[mi][0] = *(const unsigned*)ab;
                    a[mi][1] = *(const unsigned*)(ab + 8 * AS_STRIDE);
                    a[mi][2] = *(const unsigned*)(ab + 8);
                    a[mi][3] = *(const unsigned*)(ab + 8 * AS_STRIDE + 8);
                }
#pragma unroll
                for (int ni = 0; ni < 8; ++ni) {
                    const __nv_bfloat16* bb = Bs + (n0 + ni * 8 + g) * AS_STRIDE + k1 + tg * 2;
                    unsigned b0 = *(const unsigned*)bb;
                    unsigned b1 = *(const unsigned*)(bb + 8);
                    mma16816(c[0][ni], a[0], b0, b1);
                    mma16816(c[1][ni], a[1], b0, b1);
                }
            }
            __syncthreads();
        }
    }

    // epilogue: per-warp smem transpose -> coalesced stores into g_gates[dir][t][col][b]
    const float* bl = dir ? blb : blf;
    int t = bx * 4 + wm;           // warp's 32 rows = b 0..31 at this t
    float* myS = Sc + wid * (8 * 33);
    size_t gbase = (size_t)(dir * 512 + t) * (1024 * 32);
#pragma unroll
    for (int ni = 0; ni < 8; ++ni) {
#pragma unroll
        for (int mi = 0; mi < 2; ++mi)
#pragma unroll
            for (int q = 0; q < 4; ++q) {
                int col_local = tg * 2 + (q & 1);
                int row_local = mi * 16 + g + ((q >> 1) ? 8 : 0);
                myS[col_local * 33 + row_local] = c[mi][ni][q];
            }
        __syncwarp();
#pragma unroll
        for (int col = 0; col < 8; ++col) {
            int cg = c0 + n0 + ni * 8 + col;
            float v = myS[col * 33 + lane] + __ldg(&bl[cg]);
            g_gates[gbase + (size_t)cg * 32 + lane] = v;
        }
        __syncwarp();
    }
}

// ---------------- kernel 3: persistent bidirectional LSTM recurrence ----------------
__global__ void __launch_bounds__(256, 1)
k3_lstm(const float* __restrict__ Whhf, const float* __restrict__ Whhb,
        const int* __restrict__ mask) {
    __shared__ float sm[12288];           // 48 KB
    float* w_s = sm;                      // 4096 floats
    float* h_s = sm + 4096;               // 8192 floats
    float* red = sm + 4096;               // aliased: 8*528

    int cta   = blockIdx.x;
    int dir   = cta >> 6;
    int slice = cta & 63;
    int u0    = slice << 2;
    const float* Whh = dir ? Whhb : Whhf;
    int tid  = threadIdx.x;
    int warp = tid >> 5, lane = tid & 31;

    for (int i = tid; i < 4096; i += 256) {
        int k = i >> 4, lc = i & 15;
        w_s[i] = Whh[(size_t)k * 1024 + (lc >> 2) * 256 + u0 + (lc & 3)];
    }

    int u = tid >> 5;
    int b = tid & 31;
    float c_reg = 0.0f, h_reg = 0.0f, hsum_reg = 0.0f;
    if (tid < 128) g_h[0][dir][(u0 + u) * 32 + b] = 0.0f;

    unsigned base = 0;
    const unsigned* myflag = 0;
    if (tid >= 192) {
        myflag = &g_flags[dir][tid - 192];
        base = ldacq(myflag);
    }
    dir_barrier(dir, 64);

    int lc4 = (lane & 3) << 2;
    int b4  = (lane >> 2) << 2;
    int kbase = warp << 5;
    unsigned* pubflag = &g_flags[dir][slice];

    for (int t = 0; t < T_; ++t) {
        int cur = t & 1, nxt = cur ^ 1;
        int tt = dir ? (T_ - 1 - t) : t;

        float gpre0 = 0.f, gpre1 = 0.f, gpre2 = 0.f, gpre3 = 0.f, mval = 0.f;
        if (tid < 128) {
            const float* gp = g_gates + (size_t)(dir * 512 + tt) * (1024 * 32);
            gpre0 = gp[(0 * 256 + u0 + u) * 32 + b];
            gpre1 = gp[(1 * 256 + u0 + u) * 32 + b];
            gpre2 = gp[(2 * 256 + u0 + u) * 32 + b];
            gpre3 = gp[(3 * 256 + u0 + u) * 32 + b];
            mval  = (float)mask[b * T_ + tt];
        }

        if (tid >= 192) {
            unsigned need = 128u * (unsigned)t;
            while (ldacq(myflag) - base < need) { }
        }
        __syncthreads();

        {
            const float4* src = (const float4*)g_h[cur][dir];
            float4* dst = (float4*)h_s;
#pragma unroll
            for (int i = 0; i < 8; ++i) dst[tid + (i << 8)] = __ldcg(src + tid + (i << 8));
        }
        __syncthreads();

        u64 acc2[2][4];
#pragma unroll
        for (int p = 0; p < 2; ++p)
#pragma unroll
            for (int j = 0; j < 4; ++j) acc2[p][j] = 0ULL;
#pragma unroll
        for (int kk = 0; kk < 32; ++kk) {
            int k = kbase + kk;
            float4 hv = *(const float4*)&h_s[(k << 5) + b4];
            float4 wv = *(const float4*)&w_s[(k << 4) + lc4];
            u64 hp0 = pk(hv.x, hv.y), hp1 = pk(hv.z, hv.w);
            u64 wd0 = dupf(wv.x), wd1 = dupf(wv.y), wd2 = dupf(wv.z), wd3 = dupf(wv.w);
            fma2(acc2[0][0], hp0, wd0); fma2(acc2[0][1], hp0, wd1);
            fma2(acc2[0][2], hp0, wd2); fma2(acc2[0][3], hp0, wd3);
            fma2(acc2[1][0], hp1, wd0); fma2(acc2[1][1], hp1, wd1);
            fma2(acc2[1][2], hp1, wd2); fma2(acc2[1][3], hp1, wd3);
        }
        __syncthreads();
#pragma unroll
        for (int p = 0; p < 2; ++p)
#pragma unroll
            for (int j = 0; j < 4; ++j) {
                float2 v = upk(acc2[p][j]);
                red[warp * 528 + (lc4 + j) * 33 + (b4 + 2 * p + 0)] = v.x;
                red[warp * 528 + (lc4 + j) * 33 + (b4 + 2 * p + 1)] = v.y;
            }
        __syncthreads();

        if (tid < 128) {
            float z0 = gpre0, z1 = gpre1, z2 = gpre2, z3 = gpre3;
#pragma unroll
            for (int w = 0; w < 8; ++w) {
                const float* rp = red + w * 528 + b;
                z0 += rp[(0 + u) * 33];
                z1 += rp[(4 + u) * 33];
                z2 += rp[(8 + u) * 33];
                z3 += rp[(12 + u) * 33];
            }
            float ig = sigf(z0), fg = sigf(z1);
            float gg = tanhf(z2), og = sigf(z3);
            float cn = fg * c_reg + ig * gg;
            float hn = og * tanhf(cn);
            c_reg = mval * cn + (1.0f - mval) * c_reg;
            h_reg = mval * hn + (1.0f - mval) * h_reg;
            hsum_reg += mval * h_reg;
            g_h[nxt][dir][(u0 + u) * 32 + b] = h_reg;
            red_release_add1(pubflag);
        }
    }
    if (tid < 128) g_hsum[((dir << 8) + u0 + u) * 32 + b] = hsum_reg;
}

// ---------------- kernel 4a: fc_hidden[j][b], one CTA per j ----------------
__global__ void k4a_fc(const float* __restrict__ Wfc, const float* __restrict__ bfc,
                       const int* __restrict__ lengths) {
    __shared__ float redsm[8][32];
    int j = blockIdx.x;
    int tid = threadIdx.x;
    int w = tid >> 5, lane = tid & 31;
    float acc = 0.0f;
    int f0 = w * 64;
#pragma unroll 8
    for (int f = f0; f < f0 + 64; ++f)
        acc += g_hsum[f * 32 + lane] * Wfc[(size_t)f * 256 + j];
    redsm[w][lane] = acc;
    __syncthreads();
    if (w == 0) {
        float s = 0.0f;
#pragma unroll
        for (int q = 0; q < 8; ++q) s += redsm[q][lane];
        float invlen = 1.0f / (float)lengths[lane];
        g_fc[j * 32 + lane] = fmaxf(s * invlen + bfc[j], 0.0f);
    }
}

// ---------------- kernel 4b: logits ----------------
__global__ void k4b_out(const float* __restrict__ Wout, const float* __restrict__ bout,
                        float* __restrict__ out) {
    int t = threadIdx.x;
    int b = t >> 1, lab = t & 1;
    float s = bout[lab];
#pragma unroll 8
    for (int j = 0; j < 256; ++j)
        s += g_fc[j * 32 + b] * Wout[j * 2 + lab];
    out[b * 2 + lab] = s;
}

// ---------------- launch ----------------
extern "C" void kernel_launch(void* const* d_in, const int* in_sizes, int n_in,
                              void* d_out, int out_size) {
    const float* emb  = (const float*)d_in[0];
    const float* Win  = (const float*)d_in[1];
    const float* bin  = (const float*)d_in[2];
    const float* Wihf = (const float*)d_in[3];
    const float* Whhf = (const float*)d_in[4];
    const float* blf  = (const float*)d_in[5];
    const float* Wihb = (const float*)d_in[6];
    const float* Whhb = (const float*)d_in[7];
    const float* blb  = (const float*)d_in[8];
    const float* Wfc  = (const float*)d_in[9];
    const float* bfc  = (const float*)d_in[10];
    const float* Wout = (const float*)d_in[11];
    const float* bout = (const float*)d_in[12];
    const int*   x    = (const int*)d_in[13];
    const int*   mask = (const int*)d_in[14];
    const int*   len  = (const int*)d_in[15];
    float* out = (float*)d_out;

    k1_embed<<<dim3(256, 4), 256>>>(emb, Win, bin, x);
    k2w_conv<<<2048, 256>>>(Wihf, Wihb);
    k2_hmma<<<dim3(128, 16), 256>>>(blf, blb);
    k3_lstm<<<128, 256>>>(Whhf, Whhb, mask);
    k4a_fc<<<256, 256>>>(Wfc, bfc, len);
    k4b_out<<<1, 64>>>(Wout, bout, out);
}